// round 3
// baseline (speedup 1.0000x reference)
#include <cuda_runtime.h>
#include <cuda_fp16.h>
#include <math.h>

#define T_STEPS 8192
#define HID     2048
#define EMB     512
#define NCH     256
#define GRID_B  148
#define NTHR_B  512

// Static device scratch (no allocations allowed)
__device__ __half   g_H[(T_STEPS + 1) * HID];   // h history (fp16), row t = h_t; row 0 = zeros
__device__ float    g_Gc[NCH * 4 * HID];        // per-character gate preactivation (x-part + bias)
__device__ unsigned g_bar;                       // monotonic grid barrier counter

// ---------------------------------------------------------------------------
// Init: zero h_0, reset barrier
// ---------------------------------------------------------------------------
__global__ void init_kernel() {
    int i = blockIdx.x * blockDim.x + threadIdx.x;
    if (i < HID) g_H[i] = __float2half(0.f);
    if (i == 0)  g_bar = 0u;
}

// ---------------------------------------------------------------------------
// G_char[c][row] = sum_k emb[c][k] * W_gate[j][k] + b_gate[j]
// rows: [0,2048)=f, [2048,4096)=i, [4096,6144)=c~, [6144,8192)=o
// M = 8192 gate-rows, N = 256 chars, K = 512. Tiled 64x64x16 fp32 GEMM.
// ---------------------------------------------------------------------------
__global__ __launch_bounds__(256) void gchar_kernel(
    const float* __restrict__ Wf, const float* __restrict__ Wi,
    const float* __restrict__ Wc, const float* __restrict__ Wo,
    const float* __restrict__ bf, const float* __restrict__ bi,
    const float* __restrict__ bc, const float* __restrict__ bo,
    const float* __restrict__ emb)
{
    __shared__ float As[16][64];
    __shared__ float Bs[16][64];
    int m0 = blockIdx.x * 64;     // gate-row base
    int n0 = blockIdx.y * 64;     // char base
    int gate = m0 >> 11;
    int jr0  = m0 & 2047;
    const float* W    = (gate == 0) ? Wf : (gate == 1) ? Wi : (gate == 2) ? Wc : Wo;
    const float* bias = (gate == 0) ? bf : (gate == 1) ? bi : (gate == 2) ? bc : bo;

    int t  = threadIdx.x;
    int lm = t >> 2, lk = (t & 3) * 4;
    int tm = (t & 15) * 4, tn = (t >> 4) * 4;
    float acc[4][4] = {};

    for (int kt = 0; kt < EMB; kt += 16) {
        float4 va = *(const float4*)(W   + (size_t)(jr0 + lm) * 2560 + kt + lk); // x-part cols [0,512)
        float4 vb = *(const float4*)(emb + (size_t)(n0 + lm) * EMB  + kt + lk);
        __syncthreads();
        As[lk + 0][lm] = va.x; As[lk + 1][lm] = va.y; As[lk + 2][lm] = va.z; As[lk + 3][lm] = va.w;
        Bs[lk + 0][lm] = vb.x; Bs[lk + 1][lm] = vb.y; Bs[lk + 2][lm] = vb.z; Bs[lk + 3][lm] = vb.w;
        __syncthreads();
#pragma unroll
        for (int k = 0; k < 16; k++) {
            float4 a = *(const float4*)&As[k][tm];
            float4 b = *(const float4*)&Bs[k][tn];
            acc[0][0] = fmaf(a.x, b.x, acc[0][0]); acc[0][1] = fmaf(a.x, b.y, acc[0][1]);
            acc[0][2] = fmaf(a.x, b.z, acc[0][2]); acc[0][3] = fmaf(a.x, b.w, acc[0][3]);
            acc[1][0] = fmaf(a.y, b.x, acc[1][0]); acc[1][1] = fmaf(a.y, b.y, acc[1][1]);
            acc[1][2] = fmaf(a.y, b.z, acc[1][2]); acc[1][3] = fmaf(a.y, b.w, acc[1][3]);
            acc[2][0] = fmaf(a.z, b.x, acc[2][0]); acc[2][1] = fmaf(a.z, b.y, acc[2][1]);
            acc[2][2] = fmaf(a.z, b.z, acc[2][2]); acc[2][3] = fmaf(a.z, b.w, acc[2][3]);
            acc[3][0] = fmaf(a.w, b.x, acc[3][0]); acc[3][1] = fmaf(a.w, b.y, acc[3][1]);
            acc[3][2] = fmaf(a.w, b.z, acc[3][2]); acc[3][3] = fmaf(a.w, b.w, acc[3][3]);
        }
    }
#pragma unroll
    for (int i = 0; i < 4; i++) {
        float bv = bias[jr0 + tm + i];
#pragma unroll
        for (int j = 0; j < 4; j++)
            g_Gc[(size_t)(n0 + tn + j) * (4 * HID) + (m0 + tm + i)] = acc[i][j] + bv;
    }
}

// ---------------------------------------------------------------------------
// Persistent recurrent kernel. 148 CTAs, 512 threads, 1 CTA/SM (smem-bound).
// CTA b owns J h-elements (14 for b<124, else 13) => R=4J gate rows.
// Wh slice (h-part columns [512,2560)) lives in smem as fp16 row-major.
// Per step: read full h_t (fp16) from g_H via L2, warp-per-row dots,
// gate nonlinearities + c/h update for owned j's, publish h_{t+1}, grid barrier.
// ---------------------------------------------------------------------------
__global__ __launch_bounds__(NTHR_B, 1) void lstm_kernel(
    const int*   __restrict__ seq,
    const float* __restrict__ Wf, const float* __restrict__ Wi,
    const float* __restrict__ Wc, const float* __restrict__ Wo,
    float* __restrict__ out)
{
    extern __shared__ char smem[];
    int b = blockIdx.x;
    int J     = (b < 124) ? 14 : 13;
    int jbase = (b < 124) ? 14 * b : 14 * 124 + 13 * (b - 124);
    int R = 4 * J;

    __half* wsm = (__half*)smem;                        // R * 2048 halves
    float*  gsm = (float*)(smem + (size_t)R * 2 * HID); // R gate preacts

    // Prologue: load this CTA's Wh slice as fp16. 512 thr * 4 floats = 1 row/pass.
    for (int r = 0; r < R; r++) {
        int gate = r & 3, jj = r >> 2;
        const float* src =
            ((gate == 0) ? Wf : (gate == 1) ? Wi : (gate == 2) ? Wc : Wo)
            + (size_t)(jbase + jj) * 2560 + 512;
        int k = threadIdx.x * 4;
        float4 v = *(const float4*)(src + k);
        *(__half2*)(wsm + (size_t)r * HID + k)     = __floats2half2_rn(v.x, v.y);
        *(__half2*)(wsm + (size_t)r * HID + k + 2) = __floats2half2_rn(v.z, v.w);
    }
    __syncthreads();

    int w = threadIdx.x >> 5, lane = threadIdx.x & 31;
    float c_state = 0.f;
    unsigned target = 0;

    for (int t = 0; t < T_STEPS; t++) {
        int ch = __ldg(seq + t);
        const __half* hrow = g_H + (size_t)t * HID;

        // Load full h_t (fp16) into fp32 registers: lane covers k = 8*lane + 256*i
        float hv[64];
#pragma unroll
        for (int i = 0; i < 8; i++) {
            uint4 hq = *(const uint4*)(hrow + 256 * i + 8 * lane); // 8 halves
            float2 h0 = __half22float2(*(__half2*)&hq.x);
            float2 h1 = __half22float2(*(__half2*)&hq.y);
            float2 h2 = __half22float2(*(__half2*)&hq.z);
            float2 h3 = __half22float2(*(__half2*)&hq.w);
            hv[8 * i + 0] = h0.x; hv[8 * i + 1] = h0.y;
            hv[8 * i + 2] = h1.x; hv[8 * i + 3] = h1.y;
            hv[8 * i + 4] = h2.x; hv[8 * i + 5] = h2.y;
            hv[8 * i + 6] = h3.x; hv[8 * i + 7] = h3.y;
        }

        const float* gcrow = g_Gc + (size_t)ch * (4 * HID);

        // Warp-per-row dot products (rows strided by 16 warps)
        for (int r = w; r < R; r += 16) {
            int gate = r & 3, jj = r >> 2;
            float gx = gcrow[(gate << 11) + jbase + jj];
            const __half2* wr = (const __half2*)(wsm + (size_t)r * HID);
            float acc = 0.f;
#pragma unroll
            for (int i = 0; i < 8; i++) {
                uint4 wv = *(const uint4*)(wr + 128 * i + 4 * lane); // 8 halves
                float2 f0 = __half22float2(*(__half2*)&wv.x);
                float2 f1 = __half22float2(*(__half2*)&wv.y);
                float2 f2 = __half22float2(*(__half2*)&wv.z);
                float2 f3 = __half22float2(*(__half2*)&wv.w);
                acc = fmaf(f0.x, hv[8 * i + 0], acc);
                acc = fmaf(f0.y, hv[8 * i + 1], acc);
                acc = fmaf(f1.x, hv[8 * i + 2], acc);
                acc = fmaf(f1.y, hv[8 * i + 3], acc);
                acc = fmaf(f2.x, hv[8 * i + 4], acc);
                acc = fmaf(f2.y, hv[8 * i + 5], acc);
                acc = fmaf(f3.x, hv[8 * i + 6], acc);
                acc = fmaf(f3.y, hv[8 * i + 7], acc);
            }
#pragma unroll
            for (int off = 16; off > 0; off >>= 1)
                acc += __shfl_xor_sync(0xFFFFFFFFu, acc, off);
            if (lane == 0) gsm[r] = acc + gx;
        }
        __syncthreads();

        // Gate nonlinearities + state update for owned j's
        if (threadIdx.x < (unsigned)J) {
            int j = threadIdx.x;
            float gf = gsm[4 * j + 0], gi = gsm[4 * j + 1];
            float gc = gsm[4 * j + 2], go = gsm[4 * j + 3];
            float f  = 1.f / (1.f + expf(-gf));
            float ii = 1.f / (1.f + expf(-gi));
            float ct = tanhf(gc);
            float o  = 1.f / (1.f + expf(-go));
            c_state = f * c_state + ii * ct;
            float hval = o * tanhf(c_state);
            g_H[(size_t)(t + 1) * HID + jbase + j] = __float2half(hval);
            if (t == T_STEPS - 1) {
                out[(size_t)T_STEPS * NCH + jbase + j]       = hval;    // h output
                out[(size_t)T_STEPS * NCH + HID + jbase + j] = c_state; // c output
            }
        }
        __syncthreads();

        // Grid barrier: monotonic counter, release via fence+atomic, acquire poll
        target += GRID_B;
        if (threadIdx.x == 0) {
            __threadfence();
            atomicAdd(&g_bar, 1u);
            unsigned v;
            do {
                asm volatile("ld.acquire.gpu.u32 %0, [%1];" : "=r"(v) : "l"(&g_bar) : "memory");
            } while (v < target);
        }
        __syncthreads();
    }
}

// ---------------------------------------------------------------------------
// Y[t][n] = sum_k H[t+1][k] * Wy[n][k] + by[n].  M=8192, N=256, K=2048.
// H is fp16, Wy fp32, accumulate fp32.
// ---------------------------------------------------------------------------
__global__ __launch_bounds__(256) void ygemm_kernel(
    const float* __restrict__ Wy, const float* __restrict__ by,
    float* __restrict__ out)
{
    __shared__ float As[16][64];
    __shared__ float Bs[16][64];
    int m0 = blockIdx.x * 64;   // time index
    int n0 = blockIdx.y * 64;   // class index
    int t  = threadIdx.x;
    int lm = t >> 2, lk = (t & 3) * 4;
    int tm = (t & 15) * 4, tn = (t >> 4) * 4;
    float acc[4][4] = {};

    for (int kt = 0; kt < HID; kt += 16) {
        uint2 ha = *(const uint2*)(g_H + (size_t)(m0 + lm + 1) * HID + kt + lk); // 4 halves
        float2 a01 = __half22float2(*(__half2*)&ha.x);
        float2 a23 = __half22float2(*(__half2*)&ha.y);
        float4 vb = *(const float4*)(Wy + (size_t)(n0 + lm) * HID + kt + lk);
        __syncthreads();
        As[lk + 0][lm] = a01.x; As[lk + 1][lm] = a01.y; As[lk + 2][lm] = a23.x; As[lk + 3][lm] = a23.y;
        Bs[lk + 0][lm] = vb.x;  Bs[lk + 1][lm] = vb.y;  Bs[lk + 2][lm] = vb.z;  Bs[lk + 3][lm] = vb.w;
        __syncthreads();
#pragma unroll
        for (int k = 0; k < 16; k++) {
            float4 a = *(const float4*)&As[k][tm];
            float4 b = *(const float4*)&Bs[k][tn];
            acc[0][0] = fmaf(a.x, b.x, acc[0][0]); acc[0][1] = fmaf(a.x, b.y, acc[0][1]);
            acc[0][2] = fmaf(a.x, b.z, acc[0][2]); acc[0][3] = fmaf(a.x, b.w, acc[0][3]);
            acc[1][0] = fmaf(a.y, b.x, acc[1][0]); acc[1][1] = fmaf(a.y, b.y, acc[1][1]);
            acc[1][2] = fmaf(a.y, b.z, acc[1][2]); acc[1][3] = fmaf(a.y, b.w, acc[1][3]);
            acc[2][0] = fmaf(a.z, b.x, acc[2][0]); acc[2][1] = fmaf(a.z, b.y, acc[2][1]);
            acc[2][2] = fmaf(a.z, b.z, acc[2][2]); acc[2][3] = fmaf(a.z, b.w, acc[2][3]);
            acc[3][0] = fmaf(a.w, b.x, acc[3][0]); acc[3][1] = fmaf(a.w, b.y, acc[3][1]);
            acc[3][2] = fmaf(a.w, b.z, acc[3][2]); acc[3][3] = fmaf(a.w, b.w, acc[3][3]);
        }
    }
#pragma unroll
    for (int i = 0; i < 4; i++)
#pragma unroll
        for (int j = 0; j < 4; j++)
            out[(size_t)(m0 + tm + i) * NCH + n0 + tn + j] = acc[i][j] + by[n0 + tn + j];
}

// ---------------------------------------------------------------------------
extern "C" void kernel_launch(void* const* d_in, const int* in_sizes, int n_in,
                              void* d_out, int out_size)
{
    const int*   seq = (const int*)  d_in[0];
    const float* emb = (const float*)d_in[1];
    const float* Wf  = (const float*)d_in[2];
    const float* bf  = (const float*)d_in[3];
    const float* Wi  = (const float*)d_in[4];
    const float* bi  = (const float*)d_in[5];
    const float* Wo  = (const float*)d_in[6];
    const float* bo  = (const float*)d_in[7];
    const float* Wc  = (const float*)d_in[8];
    const float* bc  = (const float*)d_in[9];
    const float* Wy  = (const float*)d_in[10];
    const float* by  = (const float*)d_in[11];
    float* out = (float*)d_out;

    // 56 rows * 4096 B (fp16 weights) + gate staging
    size_t smemB = (size_t)56 * 4096 + 256;
    cudaFuncSetAttribute(lstm_kernel, cudaFuncAttributeMaxDynamicSharedMemorySize, (int)smemB);

    init_kernel<<<4, 512>>>();
    dim3 gA(4 * HID / 64, NCH / 64);
    gchar_kernel<<<gA, 256>>>(Wf, Wi, Wc, Wo, bf, bi, bc, bo, emb);
    lstm_kernel<<<GRID_B, NTHR_B, smemB>>>(seq, Wf, Wi, Wc, Wo, out);
    dim3 gC(T_STEPS / 64, NCH / 64);
    ygemm_kernel<<<gC, 256>>>(Wy, by, out);
}

// round 8
// speedup vs baseline: 1.0133x; 1.0133x over previous
#include <cuda_runtime.h>
#include <cuda_fp16.h>
#include <math.h>

#define T_STEPS 8192
#define HID     2048
#define EMB     512
#define NCH     256
#define GRID_B  148
#define NTHR_B  512

// Weight smem: 3 full 16-row blocks (64KB each) + 1 half block (8 rows, 32KB)
#define WBYTES      229376
#define SCRATCH_OFF WBYTES
#define SMEM_TOTAL  (WBYTES + 4*64*4)   // + scratch [4 kslices][64 rows] fp32

// Static device scratch (no allocations allowed)
__device__ __half   g_H[(T_STEPS + 1) * HID];   // h history (fp16); row 0 = zeros
__device__ float    g_Gc[NCH * 4 * HID];        // per-char gate preactivation (x-part + bias)
__device__ unsigned g_bar;                       // monotonic grid barrier counter

__device__ __forceinline__ float fast_sigmoid(float x) {
    x = fminf(fmaxf(x, -30.f), 30.f);
    return 1.f / (1.f + __expf(-x));
}
__device__ __forceinline__ float fast_tanh(float x) {
    float cx = fminf(fmaxf(x, -15.f), 15.f);
    float e = __expf(2.f * cx);
    return (e - 1.f) / (e + 1.f);
}

// ---------------------------------------------------------------------------
__global__ void init_kernel() {
    int i = blockIdx.x * blockDim.x + threadIdx.x;
    if (i < HID) g_H[i] = __float2half(0.f);
    if (i == 0)  g_bar = 0u;
}

// ---------------------------------------------------------------------------
// G_char[c][row] = emb[c] . W_gate_row + b ; rows: f,i,c~,o blocks of 2048.
// M=8192, N=256, K=512 fp32 GEMM, 64x64 tiles.
// ---------------------------------------------------------------------------
__global__ __launch_bounds__(256) void gchar_kernel(
    const float* __restrict__ Wf, const float* __restrict__ Wi,
    const float* __restrict__ Wc, const float* __restrict__ Wo,
    const float* __restrict__ bf, const float* __restrict__ bi,
    const float* __restrict__ bc, const float* __restrict__ bo,
    const float* __restrict__ emb)
{
    __shared__ float As[16][64];
    __shared__ float Bs[16][64];
    int m0 = blockIdx.x * 64, n0 = blockIdx.y * 64;
    int gate = m0 >> 11, jr0 = m0 & 2047;
    const float* W    = (gate == 0) ? Wf : (gate == 1) ? Wi : (gate == 2) ? Wc : Wo;
    const float* bias = (gate == 0) ? bf : (gate == 1) ? bi : (gate == 2) ? bc : bo;

    int t = threadIdx.x;
    int lm = t >> 2, lk = (t & 3) * 4;
    int tm = (t & 15) * 4, tn = (t >> 4) * 4;
    float acc[4][4] = {};

    for (int kt = 0; kt < EMB; kt += 16) {
        float4 va = *(const float4*)(W   + (size_t)(jr0 + lm) * 2560 + kt + lk);
        float4 vb = *(const float4*)(emb + (size_t)(n0 + lm) * EMB  + kt + lk);
        __syncthreads();
        As[lk + 0][lm] = va.x; As[lk + 1][lm] = va.y; As[lk + 2][lm] = va.z; As[lk + 3][lm] = va.w;
        Bs[lk + 0][lm] = vb.x; Bs[lk + 1][lm] = vb.y; Bs[lk + 2][lm] = vb.z; Bs[lk + 3][lm] = vb.w;
        __syncthreads();
#pragma unroll
        for (int k = 0; k < 16; k++) {
            float4 a = *(const float4*)&As[k][tm];
            float4 b = *(const float4*)&Bs[k][tn];
            acc[0][0] = fmaf(a.x, b.x, acc[0][0]); acc[0][1] = fmaf(a.x, b.y, acc[0][1]);
            acc[0][2] = fmaf(a.x, b.z, acc[0][2]); acc[0][3] = fmaf(a.x, b.w, acc[0][3]);
            acc[1][0] = fmaf(a.y, b.x, acc[1][0]); acc[1][1] = fmaf(a.y, b.y, acc[1][1]);
            acc[1][2] = fmaf(a.y, b.z, acc[1][2]); acc[1][3] = fmaf(a.y, b.w, acc[1][3]);
            acc[2][0] = fmaf(a.z, b.x, acc[2][0]); acc[2][1] = fmaf(a.z, b.y, acc[2][1]);
            acc[2][2] = fmaf(a.z, b.z, acc[2][2]); acc[2][3] = fmaf(a.z, b.w, acc[2][3]);
            acc[3][0] = fmaf(a.w, b.x, acc[3][0]); acc[3][1] = fmaf(a.w, b.y, acc[3][1]);
            acc[3][2] = fmaf(a.w, b.z, acc[3][2]); acc[3][3] = fmaf(a.w, b.w, acc[3][3]);
        }
    }
#pragma unroll
    for (int i = 0; i < 4; i++) {
        float bv = bias[jr0 + tm + i];
#pragma unroll
        for (int j = 0; j < 4; j++)
            g_Gc[(size_t)(n0 + tn + j) * (4 * HID) + (m0 + tm + i)] = acc[i][j] + bv;
    }
}

// ---------------------------------------------------------------------------
// Persistent recurrent kernel, tensor-core edition.
// 148 CTAs x 512 thr. CTA owns J h-units (14/13), R=4J gate rows.
// Weights fp16 in smem, ldmatrix tile layout:
//   full block b<3 (16 rows): base b*65536; k-chunk cc: +cc*512;
//     quad q=(rr>>3)+2*(kk>>3): +q*128; inner: (rr&7)*16 + (kk&7)*2
//   half block (rows 48..55): base 196608; k-chunk cc: +cc*256;
//     +((kk>>3)*128) + (rr&7)*16 + (kk&7)*2
// Warp w: row-tile w&3, K-slice (w>>2)*512. 32 mma.m16n8k16 per warp per step.
// B fragments (h, col n=0) loaded by lanes 0-3 via LDG with 8-deep prefetch.
// ---------------------------------------------------------------------------
__global__ __launch_bounds__(NTHR_B, 1) void lstm_kernel(
    const int*   __restrict__ seq,
    const float* __restrict__ Wf, const float* __restrict__ Wi,
    const float* __restrict__ Wc, const float* __restrict__ Wo,
    float* __restrict__ out)
{
    extern __shared__ char smem[];
    int b = blockIdx.x;
    int J     = (b < 124) ? 14 : 13;
    int jbase = (b < 124) ? 14 * b : 14 * 124 + 13 * (b - 124);
    int R = 4 * J;
    int tid = threadIdx.x;

    // --- Prologue: stage Wh slice (cols [512,2560)) into HMMA tile layout ---
    for (int r = 0; r < R; r++) {
        int gate = r & 3, jj = r >> 2;
        const float* src =
            ((gate == 0) ? Wf : (gate == 1) ? Wi : (gate == 2) ? Wc : Wo)
            + (size_t)(jbase + jj) * 2560 + 512;
        int k4 = tid * 4;                 // k offset, 4 consecutive (same quad, 8B)
        float4 v = *(const float4*)(src + k4);
        int blk = r >> 4, rr = r & 15;
        int cc = k4 >> 4, kkl = k4 & 15;
        int off;
        if (blk < 3)
            off = blk * 65536 + cc * 512 + ((rr >> 3) + ((kkl >> 3) << 1)) * 128
                + (rr & 7) * 16 + (kkl & 7) * 2;
        else
            off = 196608 + cc * 256 + (kkl >> 3) * 128 + (rr & 7) * 16 + (kkl & 7) * 2;
        __half2 p0 = __floats2half2_rn(v.x, v.y);
        __half2 p1 = __floats2half2_rn(v.z, v.w);
        uint2 pk; pk.x = *(unsigned*)&p0; pk.y = *(unsigned*)&p1;
        *(uint2*)(smem + off) = pk;
    }
    __syncthreads();

    unsigned smem_u32;
    asm("{ .reg .u64 t; cvta.to.shared.u64 t, %1; cvt.u32.u64 %0, t; }"
        : "=r"(smem_u32) : "l"(smem));

    int w = tid >> 5, lane = tid & 31;
    int tile = w & 3, ks = w >> 2;

    // Per-warp ldmatrix base address + step
    unsigned a_base;
    int a_step;
    if (tile < 3) {
        a_base = smem_u32 + tile * 65536 + (ks * 32) * 512
               + (lane >> 3) * 128 + (lane & 7) * 16;
        a_step = 512;
    } else {
        a_base = smem_u32 + 196608 + (ks * 32) * 256
               + ((lane >> 4) ? 128 : 0) + (lane & 7) * 16;
        a_step = 256;
    }

    float* scratch = (float*)(smem + SCRATCH_OFF);   // [4][64]
    const float4* sc4 = (const float4*)scratch;

    bool bl = (lane < 4);
    float c_state = 0.f;
    unsigned target = 0;

    for (int t = 0; t < T_STEPS; t++) {
        // gc prefetch for this step's character (warp 0, lanes < J)
        float gc0 = 0.f, gc1 = 0.f, gc2 = 0.f, gc3 = 0.f;
        if (tid < J) {
            int ch = __ldg(seq + t);
            const float* gcrow = g_Gc + (size_t)ch * (4 * HID) + jbase + tid;
            gc0 = __ldg(gcrow);
            gc1 = __ldg(gcrow + 2048);
            gc2 = __ldg(gcrow + 4096);
            gc3 = __ldg(gcrow + 6144);
        }

        // --- MMA phase: D(16x8) += A(16x16 fp16) * B(16x8 fp16), 32 k-chunks ---
        const __half* hp = g_H + (size_t)t * HID + ks * 512 + 2 * (lane & 3);
        unsigned vb0[8], vb1[8];
#pragma unroll
        for (int p = 0; p < 8; p++) {
            vb0[p] = bl ? *(const unsigned*)(hp + p * 16)     : 0u;
            vb1[p] = bl ? *(const unsigned*)(hp + p * 16 + 8) : 0u;
        }
        float d0 = 0.f, d1 = 0.f, d2 = 0.f, d3 = 0.f;
        unsigned aaddr = a_base;
#pragma unroll
        for (int blk2 = 0; blk2 < 4; blk2++) {
#pragma unroll
            for (int u = 0; u < 8; u++) {
                unsigned a0, a1, a2, a3;
                asm volatile(
                    "ldmatrix.sync.aligned.m8n8.x4.shared.b16 {%0,%1,%2,%3}, [%4];"
                    : "=r"(a0), "=r"(a1), "=r"(a2), "=r"(a3) : "r"(aaddr));
                aaddr += a_step;
                unsigned bv0 = vb0[u], bv1 = vb1[u];
                if (blk2 < 3) {
                    int cn = blk2 * 8 + u + 8;
                    vb0[u] = bl ? *(const unsigned*)(hp + cn * 16)     : 0u;
                    vb1[u] = bl ? *(const unsigned*)(hp + cn * 16 + 8) : 0u;
                }
                asm volatile(
                    "mma.sync.aligned.m16n8k16.row.col.f32.f16.f16.f32 "
                    "{%0,%1,%2,%3},{%4,%5,%6,%7},{%8,%9},{%0,%1,%2,%3};"
                    : "+f"(d0), "+f"(d1), "+f"(d2), "+f"(d3)
                    : "r"(a0), "r"(a1), "r"(a2), "r"(a3), "r"(bv0), "r"(bv1));
            }
        }
        // Column 0 of D lives in lanes with lane%4==0: d0=row(lane/4), d2=row+8
        if ((lane & 3) == 0) {
            int row = tile * 16 + (lane >> 2);
            scratch[ks * 64 + row]     = d0;
            scratch[ks * 64 + row + 8] = d2;
        }
        __syncthreads();

        // --- Gates + state update (warp 0, lanes < J) ---
        if (w == 0) {
            if (lane < J) {
                float4 s0 = sc4[0 * 16 + lane];
                float4 s1 = sc4[1 * 16 + lane];
                float4 s2 = sc4[2 * 16 + lane];
                float4 s3 = sc4[3 * 16 + lane];
                float gf = gc0 + s0.x + s1.x + s2.x + s3.x;
                float gi = gc1 + s0.y + s1.y + s2.y + s3.y;
                float gcl= gc2 + s0.z + s1.z + s2.z + s3.z;
                float go = gc3 + s0.w + s1.w + s2.w + s3.w;
                float f  = fast_sigmoid(gf);
                float ii = fast_sigmoid(gi);
                float ct = fast_tanh(gcl);
                float o  = fast_sigmoid(go);
                c_state = f * c_state + ii * ct;
                float hval = o * fast_tanh(c_state);
                g_H[(size_t)(t + 1) * HID + jbase + lane] = __float2half(hval);
                if (t == T_STEPS - 1) {
                    out[(size_t)T_STEPS * NCH + jbase + lane]       = hval;
                    out[(size_t)T_STEPS * NCH + HID + jbase + lane] = c_state;
                }
            }
            __syncwarp();
            if (lane == 0) {
                __threadfence();
                atomicAdd(&g_bar, 1u);
                unsigned tgt = target + GRID_B, v;
                do {
                    asm volatile("ld.acquire.gpu.u32 %0, [%1];"
                                 : "=r"(v) : "l"(&g_bar) : "memory");
                } while (v < tgt);
            }
        }
        target += GRID_B;
        __syncthreads();
    }
}

// ---------------------------------------------------------------------------
// Y[t][n] = H[t+1] . Wy[n] + by[n]. M=8192, N=256, K=2048. H fp16, Wy fp32.
// ---------------------------------------------------------------------------
__global__ __launch_bounds__(256) void ygemm_kernel(
    const float* __restrict__ Wy, const float* __restrict__ by,
    float* __restrict__ out)
{
    __shared__ float As[16][64];
    __shared__ float Bs[16][64];
    int m0 = blockIdx.x * 64, n0 = blockIdx.y * 64;
    int t = threadIdx.x;
    int lm = t >> 2, lk = (t & 3) * 4;
    int tm = (t & 15) * 4, tn = (t >> 4) * 4;
    float acc[4][4] = {};

    for (int kt = 0; kt < HID; kt += 16) {
        uint2 ha = *(const uint2*)(g_H + (size_t)(m0 + lm + 1) * HID + kt + lk);
        float2 a01 = __half22float2(*(__half2*)&ha.x);
        float2 a23 = __half22float2(*(__half2*)&ha.y);
        float4 vb = *(const float4*)(Wy + (size_t)(n0 + lm) * HID + kt + lk);
        __syncthreads();
        As[lk + 0][lm] = a01.x; As[lk + 1][lm] = a01.y; As[lk + 2][lm] = a23.x; As[lk + 3][lm] = a23.y;
        Bs[lk + 0][lm] = vb.x;  Bs[lk + 1][lm] = vb.y;  Bs[lk + 2][lm] = vb.z;  Bs[lk + 3][lm] = vb.w;
        __syncthreads();
#pragma unroll
        for (int k = 0; k < 16; k++) {
            float4 a = *(const float4*)&As[k][tm];
            float4 b = *(const float4*)&Bs[k][tn];
            acc[0][0] = fmaf(a.x, b.x, acc[0][0]); acc[0][1] = fmaf(a.x, b.y, acc[0][1]);
            acc[0][2] = fmaf(a.x, b.z, acc[0][2]); acc[0][3] = fmaf(a.x, b.w, acc[0][3]);
            acc[1][0] = fmaf(a.y, b.x, acc[1][0]); acc[1][1] = fmaf(a.y, b.y, acc[1][1]);
            acc[1][2] = fmaf(a.y, b.z, acc[1][2]); acc[1][3] = fmaf(a.y, b.w, acc[1][3]);
            acc[2][0] = fmaf(a.z, b.x, acc[2][0]); acc[2][1] = fmaf(a.z, b.y, acc[2][1]);
            acc[2][2] = fmaf(a.z, b.z, acc[2][2]); acc[2][3] = fmaf(a.z, b.w, acc[2][3]);
            acc[3][0] = fmaf(a.w, b.x, acc[3][0]); acc[3][1] = fmaf(a.w, b.y, acc[3][1]);
            acc[3][2] = fmaf(a.w, b.z, acc[3][2]); acc[3][3] = fmaf(a.w, b.w, acc[3][3]);
        }
    }
#pragma unroll
    for (int i = 0; i < 4; i++)
#pragma unroll
        for (int j = 0; j < 4; j++)
            out[(size_t)(m0 + tm + i) * NCH + n0 + tn + j] = acc[i][j] + by[n0 + tn + j];
}

// ---------------------------------------------------------------------------
extern "C" void kernel_launch(void* const* d_in, const int* in_sizes, int n_in,
                              void* d_out, int out_size)
{
    const int*   seq = (const int*)  d_in[0];
    const float* emb = (const float*)d_in[1];
    const float* Wf  = (const float*)d_in[2];
    const float* bf  = (const float*)d_in[3];
    const float* Wi  = (const float*)d_in[4];
    const float* bi  = (const float*)d_in[5];
    const float* Wo  = (const float*)d_in[6];
    const float* bo  = (const float*)d_in[7];
    const float* Wc  = (const float*)d_in[8];
    const float* bc  = (const float*)d_in[9];
    const float* Wy  = (const float*)d_in[10];
    const float* by  = (const float*)d_in[11];
    float* out = (float*)d_out;

    cudaFuncSetAttribute(lstm_kernel, cudaFuncAttributeMaxDynamicSharedMemorySize, SMEM_TOTAL);

    init_kernel<<<4, 512>>>();
    dim3 gA(4 * HID / 64, NCH / 64);
    gchar_kernel<<<gA, 256>>>(Wf, Wi, Wc, Wo, bf, bi, bc, bo, emb);
    lstm_kernel<<<GRID_B, NTHR_B, SMEM_TOTAL>>>(seq, Wf, Wi, Wc, Wo, out);
    dim3 gC(T_STEPS / 64, NCH / 64);
    ygemm_kernel<<<gC, 256>>>(Wy, by, out);
}